// round 9
// baseline (speedup 1.0000x reference)
#include <cuda_runtime.h>
#include <cuda_bf16.h>
#include <cuda_fp16.h>

#define Bn   64
#define Tn   1024
#define INDIM 7
#define EMB  64
#define NH   2
#define DHd  32

// ---------------- scratch (static device globals; no allocations) ----------------
__device__ __nv_bfloat16 g_q[Bn*NH*Tn*DHd];   // [bh][t][d], prescaled by log2e/sqrt(32)
__device__ __nv_bfloat16 g_k[Bn*NH*Tn*DHd];   // [bh][t][d]
__device__ __half        g_vt[Bn*NH*DHd*Tn];  // [bh][d][t]  (V transposed, f16)
__device__ float g_attn[Bn*Tn*EMB];           // attn_out
__device__ int   g_start[Bn*Tn];
__device__ int   g_nseg[Bn];
__device__ int   g_first[Bn*(Tn+1)];          // segment start positions per batch
__device__ float g_wc[192*INDIM];             // folded qkv weight [192][7]
__device__ float g_bc[192];                   // folded qkv bias

__device__ __forceinline__ unsigned packbf(float x, float y) {
    __nv_bfloat162 h = __floats2bfloat162_rn(x, y);
    return *(unsigned*)&h;
}
__device__ __forceinline__ unsigned packh(float x, float y) {  // lo=x, hi=y (f16x2)
    unsigned r;
    asm("cvt.rn.f16x2.f32 %0, %1, %2;" : "=r"(r) : "f"(y), "f"(x));
    return r;
}
__device__ __forceinline__ unsigned ex2h2(unsigned v) {
    unsigned r; asm("ex2.approx.f16x2 %0, %1;" : "=r"(r) : "r"(v)); return r;
}
__device__ __forceinline__ unsigned tf32r(float f) {
    unsigned r; asm("cvt.rna.tf32.f32 %0, %1;" : "=r"(r) : "f"(f)); return r;
}
__device__ __forceinline__ void mma_bf(float* d, const unsigned* a, unsigned b0, unsigned b1) {
    asm volatile(
        "mma.sync.aligned.m16n8k16.row.col.f32.bf16.bf16.f32 "
        "{%0,%1,%2,%3}, {%4,%5,%6,%7}, {%8,%9}, {%0,%1,%2,%3};\n"
        : "+f"(d[0]), "+f"(d[1]), "+f"(d[2]), "+f"(d[3])
        : "r"(a[0]), "r"(a[1]), "r"(a[2]), "r"(a[3]), "r"(b0), "r"(b1));
}
__device__ __forceinline__ void mma_f16(float* d, const unsigned* a, unsigned b0, unsigned b1) {
    asm volatile(
        "mma.sync.aligned.m16n8k16.row.col.f32.f16.f16.f32 "
        "{%0,%1,%2,%3}, {%4,%5,%6,%7}, {%8,%9}, {%0,%1,%2,%3};\n"
        : "+f"(d[0]), "+f"(d[1]), "+f"(d[2]), "+f"(d[3])
        : "r"(a[0]), "r"(a[1]), "r"(a[2]), "r"(a[3]), "r"(b0), "r"(b1));
}
__device__ __forceinline__ void mma_tf(float* d, const unsigned* a, unsigned b0, unsigned b1) {
    asm volatile(
        "mma.sync.aligned.m16n8k8.row.col.f32.tf32.tf32.f32 "
        "{%0,%1,%2,%3}, {%4,%5,%6,%7}, {%8,%9}, {%0,%1,%2,%3};\n"
        : "+f"(d[0]), "+f"(d[1]), "+f"(d[2]), "+f"(d[3])
        : "r"(a[0]), "r"(a[1]), "r"(a[2]), "r"(a[3]), "r"(b0), "r"(b1));
}
__device__ __forceinline__ void cpa16(unsigned dst, const void* src) {
    asm volatile("cp.async.cg.shared.global [%0], [%1], 16;\n" :: "r"(dst), "l"(src));
}
__device__ __forceinline__ void cp_commit() { asm volatile("cp.async.commit_group;\n"); }

// ---------------- K0: fold the two input linears into one 7->192 ----------------
__global__ __launch_bounds__(256) void k0_fold(
    const float* __restrict__ w_in, const float* __restrict__ b_in,
    const float* __restrict__ ipw, const float* __restrict__ ipb)
{
    const int gid = blockIdx.x * 256 + threadIdx.x;
    if (gid < 192 * INDIM) {
        const int o = gid / INDIM, j = gid % INDIM;
        float s = 0.f;
#pragma unroll
        for (int e = 0; e < 64; e++) s += ipw[o*64 + e] * w_in[e*INDIM + j];
        g_wc[gid] = s;
    } else if (gid < 192 * INDIM + 192) {
        const int o = gid - 192 * INDIM;
        float s = ipb[o];
#pragma unroll
        for (int e = 0; e < 64; e++) s += ipw[o*64 + e] * b_in[e];
        g_bc[o] = s;
    }
}

// ---------------- K1: x -> qkv via folded weights (q,k bf16; v f16 transposed) ----
__global__ __launch_bounds__(128) void k1_qkv(const float* __restrict__ x)
{
    extern __shared__ float sm[];
    float* s_wc = sm;                 // 1344
    float* s_bc = s_wc + 192*INDIM;   // 192
    unsigned short* s_qkv = (unsigned short*)(s_bc + 192);  // 128 x 194 raw 16-bit

    const int tid = threadIdx.x;
    for (int i = tid; i < 192*INDIM; i += 128) s_wc[i] = g_wc[i];
    for (int i = tid; i < 192;       i += 128) s_bc[i] = g_bc[i];
    __syncthreads();

    const int pos = blockIdx.x * 128 + tid;
    float xv[INDIM];
    const float* xp = x + (size_t)pos * INDIM;
#pragma unroll
    for (int j = 0; j < INDIM; j++) xv[j] = xp[j];

    const float QSCALE = 0.25506363f;  // log2(e)/sqrt(32)
    unsigned short* row = s_qkv + tid * 194;
#pragma unroll
    for (int j0 = 0; j0 < 192; j0 += 4) {
        float a0 = s_bc[j0], a1 = s_bc[j0+1], a2 = s_bc[j0+2], a3 = s_bc[j0+3];
#pragma unroll
        for (int j = 0; j < INDIM; j++) {
            float xj = xv[j];
            a0 += s_wc[(j0+0)*INDIM + j] * xj;
            a1 += s_wc[(j0+1)*INDIM + j] * xj;
            a2 += s_wc[(j0+2)*INDIM + j] * xj;
            a3 += s_wc[(j0+3)*INDIM + j] * xj;
        }
        if (j0 < 64) { a0 *= QSCALE; a1 *= QSCALE; a2 *= QSCALE; a3 *= QSCALE; }
        if (j0 < 128) {   // q,k -> bf16
            *(unsigned*)&row[j0]     = packbf(a0, a1);
            *(unsigned*)&row[j0 + 2] = packbf(a2, a3);
        } else {          // v -> f16
            *(unsigned*)&row[j0]     = packh(a0, a1);
            *(unsigned*)&row[j0 + 2] = packh(a2, a3);
        }
    }
    __syncthreads();

    const int b  = blockIdx.x >> 3;
    const int t0 = (blockIdx.x & 7) * 128;
    unsigned* uq = (unsigned*)g_q;
    unsigned* uk = (unsigned*)g_k;
#pragma unroll
    for (int hh = 0; hh < 2; hh++) {
        const int dst = (b*2 + hh) * (Tn*DHd/2) + t0 * 16;
        for (int l2 = tid; l2 < 2048; l2 += 128) {
            int tt = l2 >> 4, dp = l2 & 15;
            const unsigned short* r = s_qkv + tt * 194;
            uq[dst + l2] = *(const unsigned*)&r[       hh*32 + dp*2];
            uk[dst + l2] = *(const unsigned*)&r[ 64  + hh*32 + dp*2];
        }
    }
    // V transposed writeout: g_vt[bh][d][t]
    unsigned* uvt = (unsigned*)g_vt;
    for (int idx = tid; idx < 4096; idx += 128) {
        int p = idx >> 6, tp = idx & 63;
        int hh = p >> 5, d = p & 31;
        unsigned short lo = s_qkv[(2*tp    ) * 194 + 128 + hh*32 + d];
        unsigned short hi = s_qkv[(2*tp + 1) * 194 + 128 + hh*32 + d];
        uvt[(b*2 + hh) * 16384 + d * 512 + (t0 >> 1) + tp] =
            (unsigned)lo | ((unsigned)hi << 16);
    }
}

// ---------------- K2: fused flash attention (both heads) + out-proj + MLP ------
// Block = (q-tile, batch), 256 threads. Heads processed sequentially; each warp
// then owns complete 64-dim ctx rows -> tf32 out-proj + boundary MLP inline.
#define BQ 128
#define BK 64
#define NT (Tn / BK)
// smem union layout (bytes from base):
//   s_cx  float[128][68]                      [0, 34816)
//   flash view (offset 34816):
//     Qs bf16[128][40]   10240
//     Ks bf16[2][64][40] 10240
//     Vt f16 [2][32][72]  9216     -> 29696
//   weight view (offset 34816):
//     s_owp f32[64*68] 17408 | s_w1p f32[32*68] 8704 | ob 256 | b1 128 | w2 128 | b2 4
#define SM2_TOTAL (34816 + 29696)
__global__ __launch_bounds__(256) void k2_fused(
    const float* __restrict__ ow, const float* __restrict__ ob,
    const float* __restrict__ w1, const float* __restrict__ b1,
    const float* __restrict__ w2, const float* __restrict__ b2p)
{
    extern __shared__ char smem2[];
    float (*s_cx)[68] = (float(*)[68])smem2;
    char* uni = smem2 + 34816;
    __nv_bfloat16* QsB = (__nv_bfloat16*)uni;            // [128][40]
    __nv_bfloat16* KsB = (__nv_bfloat16*)(uni + 10240);  // [2][64][40]
    __half*        VtB = (__half*)(uni + 20480);         // [2][32][72]
#define QS(r,c)    QsB[(r)*40+(c)]
#define KS(bf,r,c) KsB[(bf)*2560 + (r)*40 + (c)]
#define VT(bf,r,c) VtB[(bf)*2304 + (r)*72 + (c)]
    float* s_owp = (float*)uni;              // 64 x 68
    float* s_w1p = (float*)(uni + 17408);    // 32 x 68
    float* s_ob  = (float*)(uni + 26112);
    float* s_b1  = (float*)(uni + 26368);
    float* s_w2  = (float*)(uni + 26496);
    float* s_b2  = (float*)(uni + 26624);

    const int tid = threadIdx.x;
    const int w = tid >> 5, lane = tid & 31;
    const int g = lane >> 2, tg = lane & 3;
    const int b = blockIdx.y;
    const int q0 = blockIdx.x * BQ;
    const int r0 = w * 16;

    const int krow = tid >> 2, kchk = tid & 3;
    const int vrow = tid >> 3, vchk = tid & 7;

    float oo[2][4][4];
    float inv0[2], inv1[2];
    const unsigned ONE2 = 0x3C003C00u;

    for (int hh = 0; hh < 2; hh++) {
        const int bh = b * 2 + hh;
        const __nv_bfloat16* gkb = (const __nv_bfloat16*)g_k + (size_t)bh * Tn * 32;
        const __half*        gvb = (const __half*)g_vt + (size_t)bh * 32 * Tn;

        // prefetch tile 0 (previous head's compute finished at its last __syncthreads)
        cpa16((unsigned)__cvta_generic_to_shared(&KS(0, krow, kchk*8)),
              gkb + (size_t)krow * 32 + kchk * 8);
        cpa16((unsigned)__cvta_generic_to_shared(&VT(0, vrow, vchk*8)),
              gvb + (size_t)vrow * Tn + vchk * 8);
        cp_commit();

        // load Q tile
        const unsigned* gq = (const unsigned*)g_q + (size_t)(bh * Tn + q0) * 16;
#pragma unroll
        for (int i = 0; i < 8; i++) {
            int l2 = tid + i * 256;
            int r = l2 >> 4, c = l2 & 15;
            *(unsigned*)&QS(r, c * 2) = gq[l2];
        }
        __syncthreads();

        unsigned qa[2][4];
#pragma unroll
        for (int kb = 0; kb < 2; kb++) {
            qa[kb][0] = *(const unsigned*)&QS(r0 + g,     kb*16 + tg*2);
            qa[kb][1] = *(const unsigned*)&QS(r0 + g + 8, kb*16 + tg*2);
            qa[kb][2] = *(const unsigned*)&QS(r0 + g,     kb*16 + tg*2 + 8);
            qa[kb][3] = *(const unsigned*)&QS(r0 + g + 8, kb*16 + tg*2 + 8);
        }

        float (*o)[4] = oo[hh];
        float lsum[4] = {0.f, 0.f, 0.f, 0.f};
#pragma unroll
        for (int i = 0; i < 4; i++)
#pragma unroll
            for (int j = 0; j < 4; j++) o[i][j] = 0.f;

        for (int kt = 0; kt < NT; kt++) {
            const int buf = kt & 1;
            if (kt + 1 < NT) {
                const int nb_ = buf ^ 1;
                cpa16((unsigned)__cvta_generic_to_shared(&KS(nb_, krow, kchk*8)),
                      gkb + (size_t)((kt+1)*BK + krow) * 32 + kchk * 8);
                cpa16((unsigned)__cvta_generic_to_shared(&VT(nb_, vrow, vchk*8)),
                      gvb + (size_t)vrow * Tn + (kt+1)*BK + vchk * 8);
                cp_commit();
                asm volatile("cp.async.wait_group 1;\n");
            } else {
                asm volatile("cp.async.wait_group 0;\n");
            }
            __syncthreads();

            float s[8][4];
#pragma unroll
            for (int nb = 0; nb < 8; nb++) {
                s[nb][0] = s[nb][1] = s[nb][2] = s[nb][3] = 0.f;
#pragma unroll
                for (int kb = 0; kb < 2; kb++) {
                    unsigned b0 = *(const unsigned*)&KS(buf, nb*8 + g, kb*16 + tg*2);
                    unsigned b1v = *(const unsigned*)&KS(buf, nb*8 + g, kb*16 + tg*2 + 8);
                    mma_bf(s[nb], qa[kb], b0, b1v);
                }
            }

            unsigned pa[4][4];
#pragma unroll
            for (int kb2 = 0; kb2 < 4; kb2++) {
                pa[kb2][0] = ex2h2(packh(s[2*kb2    ][0], s[2*kb2    ][1]));
                pa[kb2][1] = ex2h2(packh(s[2*kb2    ][2], s[2*kb2    ][3]));
                pa[kb2][2] = ex2h2(packh(s[2*kb2 + 1][0], s[2*kb2 + 1][1]));
                pa[kb2][3] = ex2h2(packh(s[2*kb2 + 1][2], s[2*kb2 + 1][3]));
            }

#pragma unroll
            for (int kb2 = 0; kb2 < 4; kb2++)
                mma_f16(lsum, pa[kb2], ONE2, ONE2);

#pragma unroll
            for (int nb2 = 0; nb2 < 4; nb2++) {
#pragma unroll
                for (int kb2 = 0; kb2 < 4; kb2++) {
                    unsigned b0 = *(const unsigned*)&VT(buf, nb2*8 + g, kb2*16 + tg*2);
                    unsigned b1v = *(const unsigned*)&VT(buf, nb2*8 + g, kb2*16 + tg*2 + 8);
                    mma_f16(o[nb2], pa[kb2], b0, b1v);
                }
            }
            __syncthreads();
        }
        inv0[hh] = 1.f / lsum[0];
        inv1[hh] = 1.f / lsum[2];
    }

    // write normalized ctx into s_cx (each warp its own 16 rows; cols hh*32+..)
#pragma unroll
    for (int hh = 0; hh < 2; hh++) {
#pragma unroll
        for (int nb2 = 0; nb2 < 4; nb2++) {
            int col = hh * 32 + nb2 * 8 + tg * 2;
            s_cx[r0 + g    ][col]     = oo[hh][nb2][0] * inv0[hh];
            s_cx[r0 + g    ][col + 1] = oo[hh][nb2][1] * inv0[hh];
            s_cx[r0 + g + 8][col]     = oo[hh][nb2][2] * inv1[hh];
            s_cx[r0 + g + 8][col + 1] = oo[hh][nb2][3] * inv1[hh];
        }
    }

    // load weights into the union region (flash buffers dead after last sync)
    for (int i = tid; i < 4096; i += 256)
        s_owp[(i >> 6) * 68 + (i & 63)] = __uint_as_float(tf32r(ow[i]));
    for (int i = tid; i < 2048; i += 256)
        s_w1p[(i >> 6) * 68 + (i & 63)] = __uint_as_float(tf32r(w1[i]));
    if (tid < 64) s_ob[tid] = ob[tid];
    if (tid < 32) { s_b1[tid] = b1[tid]; s_w2[tid] = w2[tid]; }
    if (tid == 0) s_b2[0] = b2p[0];
    __syncthreads();

    const int base = b * Tn + q0;

    // A fragments (ctx), tf32
    unsigned af[8][4];
#pragma unroll
    for (int kb = 0; kb < 8; kb++) {
        af[kb][0] = tf32r(s_cx[r0 + g    ][kb*8 + tg]);
        af[kb][1] = tf32r(s_cx[r0 + g + 8][kb*8 + tg]);
        af[kb][2] = tf32r(s_cx[r0 + g    ][kb*8 + tg + 4]);
        af[kb][3] = tf32r(s_cx[r0 + g + 8][kb*8 + tg + 4]);
    }

    // GEMM1: out-proj
    float c[8][4];
#pragma unroll
    for (int nb = 0; nb < 8; nb++) {
        c[nb][0] = c[nb][1] = c[nb][2] = c[nb][3] = 0.f;
#pragma unroll
        for (int kb = 0; kb < 8; kb++) {
            unsigned b0 = __float_as_uint(s_owp[(nb*8 + g)*68 + kb*8 + tg]);
            unsigned b1v = __float_as_uint(s_owp[(nb*8 + g)*68 + kb*8 + tg + 4]);
            mma_tf(c[nb], af[kb], b0, b1v);
        }
    }

    // epilogue1: bias, write g_attn + smem (in place over own rows)
    {
        float* a0p = g_attn + (size_t)(base + r0 + g) * 64;
        float* a1p = a0p + 8 * 64;
#pragma unroll
        for (int nb = 0; nb < 8; nb++) {
            int col = nb * 8 + tg * 2;
            c[nb][0] += s_ob[col]; c[nb][1] += s_ob[col + 1];
            c[nb][2] += s_ob[col]; c[nb][3] += s_ob[col + 1];
            *(float2*)(a0p + col) = make_float2(c[nb][0], c[nb][1]);
            *(float2*)(a1p + col) = make_float2(c[nb][2], c[nb][3]);
            s_cx[r0 + g    ][col] = c[nb][0]; s_cx[r0 + g    ][col+1] = c[nb][1];
            s_cx[r0 + g + 8][col] = c[nb][2]; s_cx[r0 + g + 8][col+1] = c[nb][3];
        }
    }
    __syncwarp();

    // A fragments (attn) for GEMM2
#pragma unroll
    for (int kb = 0; kb < 8; kb++) {
        af[kb][0] = tf32r(s_cx[r0 + g    ][kb*8 + tg]);
        af[kb][1] = tf32r(s_cx[r0 + g + 8][kb*8 + tg]);
        af[kb][2] = tf32r(s_cx[r0 + g    ][kb*8 + tg + 4]);
        af[kb][3] = tf32r(s_cx[r0 + g + 8][kb*8 + tg + 4]);
    }

    // GEMM2: hidden [16 x 32]
    float h[4][4];
#pragma unroll
    for (int nb = 0; nb < 4; nb++) {
        h[nb][0] = h[nb][1] = h[nb][2] = h[nb][3] = 0.f;
#pragma unroll
        for (int kb = 0; kb < 8; kb++) {
            unsigned b0 = __float_as_uint(s_w1p[(nb*8 + g)*68 + kb*8 + tg]);
            unsigned b1v = __float_as_uint(s_w1p[(nb*8 + g)*68 + kb*8 + tg + 4]);
            mma_tf(h[nb], af[kb], b0, b1v);
        }
    }

    float z0 = 0.f, z1 = 0.f;
#pragma unroll
    for (int nb = 0; nb < 4; nb++) {
        int col = nb * 8 + tg * 2;
        z0 += s_w2[col]   * fmaxf(h[nb][0] + s_b1[col],   0.f)
            + s_w2[col+1] * fmaxf(h[nb][1] + s_b1[col+1], 0.f);
        z1 += s_w2[col]   * fmaxf(h[nb][2] + s_b1[col],   0.f)
            + s_w2[col+1] * fmaxf(h[nb][3] + s_b1[col+1], 0.f);
    }
    z0 += __shfl_xor_sync(0xffffffffu, z0, 1);
    z0 += __shfl_xor_sync(0xffffffffu, z0, 2);
    z1 += __shfl_xor_sync(0xffffffffu, z1, 1);
    z1 += __shfl_xor_sync(0xffffffffu, z1, 2);

    if (tg == 0) {
        const float b2v = s_b2[0];
        int t0 = q0 + r0 + g;
        g_start[base + r0 + g] = (t0 == 0) || (t0 <= Tn - 2 && z0 + b2v > -1.38629436f);
        int t1 = t0 + 8;
        g_start[base + r0 + g + 8] = (t1 == 0) || (t1 <= Tn - 2 && z1 + b2v > -1.38629436f);
    }
#undef QS
#undef KS
#undef VT
}

// ---------------- K4a: per-batch ballot scan -> segment boundary list ----------------
__global__ __launch_bounds__(1024) void k4a_scan()
{
    const int b = blockIdx.x;
    const int t = threadIdx.x;
    const int lane = t & 31, wid = t >> 5;
    __shared__ int s_wcnt[32];
    __shared__ int s_woff[32];

    const int v = g_start[b * Tn + t];
    const unsigned m = __ballot_sync(0xffffffffu, v);
    const int pre = __popc(m & ((1u << lane) - 1u));
    if (lane == 0) s_wcnt[wid] = __popc(m);
    __syncthreads();
    if (t < 32) {
        int c = s_wcnt[t];
        int inc = c;
#pragma unroll
        for (int off = 1; off < 32; off <<= 1) {
            int n = __shfl_up_sync(0xffffffffu, inc, off);
            if (t >= off) inc += n;
        }
        s_woff[t] = inc - c;
        if (t == 31) {
            g_nseg[b] = inc;
            g_first[b * (Tn + 1) + inc] = Tn;
        }
    }
    __syncthreads();
    if (v) g_first[b * (Tn + 1) + s_woff[wid] + pre] = t;
}

// ---------------- K4c: fused segment-mean + final projection ----------------
__global__ __launch_bounds__(256) void k4c_meanproj(
    const float* __restrict__ pw, const float* __restrict__ pb,
    float* __restrict__ out)
{
    __shared__ float s_w[64 * 65];
    __shared__ float s_b[64];
    const int tid = threadIdx.x;
    for (int i = tid; i < 4096; i += 256)
        s_w[(i >> 6) * 65 + (i & 63)] = pw[i];
    if (tid < 64) s_b[tid] = pb[tid];
    __syncthreads();

    const int b = blockIdx.x;
    const int wid = tid >> 5, lane = tid & 31;
    const int nseg = g_nseg[b];
    const int* fst = g_first + b * (Tn + 1);

    for (int s = blockIdx.y * 8 + wid; s < Tn; s += 16 * 8) {
        float* op = out + (size_t)(b * Tn + s) * 64;
        if (s >= nseg) {
            op[lane]      = s_b[lane];
            op[lane + 32] = s_b[lane + 32];
            continue;
        }
        const int t0 = fst[s], t1 = fst[s + 1];
        float f0 = 0.f, f1 = 0.f;
        for (int t = t0; t < t1; t++) {
            const float* row = g_attn + (size_t)(b * Tn + t) * 64;
            f0 += row[lane];
            f1 += row[lane + 32];
        }
        const float inv = 1.f / (float)(t1 - t0);
        f0 *= inv; f1 *= inv;

        float a0 = s_b[lane], a1 = s_b[lane + 32];
        const float* w0 = s_w + lane * 65;
        const float* w1 = s_w + (lane + 32) * 65;
#pragma unroll
        for (int d = 0; d < 32; d++) {
            float md = __shfl_sync(0xffffffffu, f0, d);
            a0 += md * w0[d];
            a1 += md * w1[d];
        }
#pragma unroll
        for (int d = 0; d < 32; d++) {
            float md = __shfl_sync(0xffffffffu, f1, d);
            a0 += md * w0[32 + d];
            a1 += md * w1[32 + d];
        }
        op[lane]      = a0;
        op[lane + 32] = a1;
    }
}

// ---------------- launch ----------------
extern "C" void kernel_launch(void* const* d_in, const int* in_sizes, int n_in,
                              void* d_out, int out_size)
{
    const float* x    = (const float*)d_in[0];
    const float* w_in = (const float*)d_in[1];
    const float* b_in = (const float*)d_in[2];
    const float* ipw  = (const float*)d_in[3];
    const float* ipb  = (const float*)d_in[4];
    const float* ow   = (const float*)d_in[5];
    const float* ob   = (const float*)d_in[6];
    const float* w1   = (const float*)d_in[7];
    const float* b1   = (const float*)d_in[8];
    const float* w2   = (const float*)d_in[9];
    const float* b2   = (const float*)d_in[10];
    const float* pw   = (const float*)d_in[11];
    const float* pb   = (const float*)d_in[12];
    float* out = (float*)d_out;

    const int smem1 = (192*INDIM + 192) * 4 + 128 * 194 * 2;  // ~55.9 KB
    cudaFuncSetAttribute(k1_qkv, cudaFuncAttributeMaxDynamicSharedMemorySize, smem1);
    cudaFuncSetAttribute(k2_fused, cudaFuncAttributeMaxDynamicSharedMemorySize, SM2_TOTAL);

    k0_fold<<<6, 256>>>(w_in, b_in, ipw, ipb);
    k1_qkv<<<(Bn * Tn) / 128, 128, smem1>>>(x);
    dim3 g2(Tn / BQ, Bn);
    k2_fused<<<g2, 256, SM2_TOTAL>>>(ow, ob, w1, b1, w2, b2);
    k4a_scan<<<Bn, 1024>>>();
    dim3 g4(Bn, 16);
    k4c_meanproj<<<g4, 256>>>(pw, pb, out);
}

// round 10
// speedup vs baseline: 1.0479x; 1.0479x over previous
#include <cuda_runtime.h>
#include <cuda_bf16.h>
#include <cuda_fp16.h>

#define Bn   64
#define Tn   1024
#define INDIM 7
#define EMB  64
#define NH   2
#define DHd  32

// ---------------- scratch (static device globals; no allocations) ----------------
__device__ __nv_bfloat16 g_q[Bn*NH*Tn*DHd];   // [bh][t][d], prescaled by log2e/sqrt(32)
__device__ __nv_bfloat16 g_k[Bn*NH*Tn*DHd];   // [bh][t][d]
__device__ __half        g_vt[Bn*NH*DHd*Tn];  // [bh][d][t]  (V transposed, f16)
__device__ float g_ctx[Bn*Tn*EMB];            // [b][t][h*32+d]
__device__ float g_attn[Bn*Tn*EMB];           // attn_out
__device__ int   g_start[Bn*Tn];
__device__ int   g_nseg[Bn];
__device__ int   g_first[Bn*(Tn+1)];          // segment start positions per batch
__device__ float g_wc[192*INDIM];             // folded qkv weight [192][7]
__device__ float g_bc[192];                   // folded qkv bias

__device__ __forceinline__ unsigned packbf(float x, float y) {
    __nv_bfloat162 h = __floats2bfloat162_rn(x, y);
    return *(unsigned*)&h;
}
__device__ __forceinline__ unsigned packh(float x, float y) {  // lo=x, hi=y (f16x2)
    unsigned r;
    asm("cvt.rn.f16x2.f32 %0, %1, %2;" : "=r"(r) : "f"(y), "f"(x));
    return r;
}
__device__ __forceinline__ unsigned ex2h2(unsigned v) {
    unsigned r; asm("ex2.approx.f16x2 %0, %1;" : "=r"(r) : "r"(v)); return r;
}
__device__ __forceinline__ unsigned tf32r(float f) {
    unsigned r; asm("cvt.rna.tf32.f32 %0, %1;" : "=r"(r) : "f"(f)); return r;
}
__device__ __forceinline__ void mma_bf(float* d, const unsigned* a, unsigned b0, unsigned b1) {
    asm volatile(
        "mma.sync.aligned.m16n8k16.row.col.f32.bf16.bf16.f32 "
        "{%0,%1,%2,%3}, {%4,%5,%6,%7}, {%8,%9}, {%0,%1,%2,%3};\n"
        : "+f"(d[0]), "+f"(d[1]), "+f"(d[2]), "+f"(d[3])
        : "r"(a[0]), "r"(a[1]), "r"(a[2]), "r"(a[3]), "r"(b0), "r"(b1));
}
__device__ __forceinline__ void mma_f16(float* d, const unsigned* a, unsigned b0, unsigned b1) {
    asm volatile(
        "mma.sync.aligned.m16n8k16.row.col.f32.f16.f16.f32 "
        "{%0,%1,%2,%3}, {%4,%5,%6,%7}, {%8,%9}, {%0,%1,%2,%3};\n"
        : "+f"(d[0]), "+f"(d[1]), "+f"(d[2]), "+f"(d[3])
        : "r"(a[0]), "r"(a[1]), "r"(a[2]), "r"(a[3]), "r"(b0), "r"(b1));
}
__device__ __forceinline__ void mma_tf(float* d, const unsigned* a, unsigned b0, unsigned b1) {
    asm volatile(
        "mma.sync.aligned.m16n8k8.row.col.f32.tf32.tf32.f32 "
        "{%0,%1,%2,%3}, {%4,%5,%6,%7}, {%8,%9}, {%0,%1,%2,%3};\n"
        : "+f"(d[0]), "+f"(d[1]), "+f"(d[2]), "+f"(d[3])
        : "r"(a[0]), "r"(a[1]), "r"(a[2]), "r"(a[3]), "r"(b0), "r"(b1));
}
__device__ __forceinline__ void ldsm4(unsigned* r, unsigned addr) {
    asm volatile("ldmatrix.sync.aligned.m8n8.x4.shared.b16 {%0,%1,%2,%3}, [%4];\n"
        : "=r"(r[0]), "=r"(r[1]), "=r"(r[2]), "=r"(r[3]) : "r"(addr));
}
__device__ __forceinline__ void cpa16(unsigned dst, const void* src) {
    asm volatile("cp.async.cg.shared.global [%0], [%1], 16;\n" :: "r"(dst), "l"(src));
}
__device__ __forceinline__ void cp_commit() { asm volatile("cp.async.commit_group;\n"); }

// ---------------- K0: fold the two input linears into one 7->192 ----------------
__global__ __launch_bounds__(256) void k0_fold(
    const float* __restrict__ w_in, const float* __restrict__ b_in,
    const float* __restrict__ ipw, const float* __restrict__ ipb)
{
    const int gid = blockIdx.x * 256 + threadIdx.x;
    if (gid < 192 * INDIM) {
        const int o = gid / INDIM, j = gid % INDIM;
        float s = 0.f;
#pragma unroll
        for (int e = 0; e < 64; e++) s += ipw[o*64 + e] * w_in[e*INDIM + j];
        g_wc[gid] = s;
    } else if (gid < 192 * INDIM + 192) {
        const int o = gid - 192 * INDIM;
        float s = ipb[o];
#pragma unroll
        for (int e = 0; e < 64; e++) s += ipw[o*64 + e] * b_in[e];
        g_bc[o] = s;
    }
}

// ---------------- K1: x -> qkv via folded weights (q,k bf16; v f16 transposed) ----
__global__ __launch_bounds__(128) void k1_qkv(const float* __restrict__ x)
{
    extern __shared__ float sm[];
    float* s_wc = sm;                 // 1344
    float* s_bc = s_wc + 192*INDIM;   // 192
    unsigned short* s_qkv = (unsigned short*)(s_bc + 192);  // 128 x 194 raw 16-bit

    const int tid = threadIdx.x;
    for (int i = tid; i < 192*INDIM; i += 128) s_wc[i] = g_wc[i];
    for (int i = tid; i < 192;       i += 128) s_bc[i] = g_bc[i];
    __syncthreads();

    const int pos = blockIdx.x * 128 + tid;
    float xv[INDIM];
    const float* xp = x + (size_t)pos * INDIM;
#pragma unroll
    for (int j = 0; j < INDIM; j++) xv[j] = xp[j];

    const float QSCALE = 0.25506363f;  // log2(e)/sqrt(32)
    unsigned short* row = s_qkv + tid * 194;
#pragma unroll
    for (int j0 = 0; j0 < 192; j0 += 4) {
        float a0 = s_bc[j0], a1 = s_bc[j0+1], a2 = s_bc[j0+2], a3 = s_bc[j0+3];
#pragma unroll
        for (int j = 0; j < INDIM; j++) {
            float xj = xv[j];
            a0 += s_wc[(j0+0)*INDIM + j] * xj;
            a1 += s_wc[(j0+1)*INDIM + j] * xj;
            a2 += s_wc[(j0+2)*INDIM + j] * xj;
            a3 += s_wc[(j0+3)*INDIM + j] * xj;
        }
        if (j0 < 64) { a0 *= QSCALE; a1 *= QSCALE; a2 *= QSCALE; a3 *= QSCALE; }
        if (j0 < 128) {   // q,k -> bf16
            *(unsigned*)&row[j0]     = packbf(a0, a1);
            *(unsigned*)&row[j0 + 2] = packbf(a2, a3);
        } else {          // v -> f16
            *(unsigned*)&row[j0]     = packh(a0, a1);
            *(unsigned*)&row[j0 + 2] = packh(a2, a3);
        }
    }
    __syncthreads();

    const int b  = blockIdx.x >> 3;
    const int t0 = (blockIdx.x & 7) * 128;
    unsigned* uq = (unsigned*)g_q;
    unsigned* uk = (unsigned*)g_k;
#pragma unroll
    for (int hh = 0; hh < 2; hh++) {
        const int dst = (b*2 + hh) * (Tn*DHd/2) + t0 * 16;
        for (int l2 = tid; l2 < 2048; l2 += 128) {
            int tt = l2 >> 4, dp = l2 & 15;
            const unsigned short* r = s_qkv + tt * 194;
            uq[dst + l2] = *(const unsigned*)&r[       hh*32 + dp*2];
            uk[dst + l2] = *(const unsigned*)&r[ 64  + hh*32 + dp*2];
        }
    }
    // V transposed writeout: g_vt[bh][d][t]
    unsigned* uvt = (unsigned*)g_vt;
    for (int idx = tid; idx < 4096; idx += 128) {
        int p = idx >> 6, tp = idx & 63;
        int hh = p >> 5, d = p & 31;
        unsigned short lo = s_qkv[(2*tp    ) * 194 + 128 + hh*32 + d];
        unsigned short hi = s_qkv[(2*tp + 1) * 194 + 128 + hh*32 + d];
        uvt[(b*2 + hh) * 16384 + d * 512 + (t0 >> 1) + tp] =
            (unsigned)lo | ((unsigned)hi << 16);
    }
}

// ---------------- K2: flash attention, ldmatrix frags, cp.async pipe ----------
#define BQ 128
#define BK 64
#define NT (Tn / BK)
__global__ __launch_bounds__(256) void k2_attn()
{
    __shared__ __nv_bfloat16 Qs[BQ][40];
    __shared__ __nv_bfloat16 Ks[2][BK][40];
    __shared__ __half        Vt[2][32][72];

    const int tid = threadIdx.x;
    const int wid = tid >> 5, lane = tid & 31;
    const int g = lane >> 2, tg = lane & 3;
    const int bh = blockIdx.y;
    const int q0 = blockIdx.x * BQ;
    const int r0 = wid * 16 + g;

    const int krow = tid >> 2, kchk = tid & 3;
    const int vrow = tid >> 3, vchk = tid & 7;
    const __nv_bfloat16* gkb = (const __nv_bfloat16*)g_k + (size_t)bh * Tn * 32;
    const __half*        gvb = (const __half*)g_vt + (size_t)bh * 32 * Tn;

    {
        cpa16((unsigned)__cvta_generic_to_shared(&Ks[0][krow][kchk*8]),
              gkb + (size_t)krow * 32 + kchk * 8);
        cpa16((unsigned)__cvta_generic_to_shared(&Vt[0][vrow][vchk*8]),
              gvb + (size_t)vrow * Tn + vchk * 8);
        cp_commit();
    }

    const unsigned* gq = (const unsigned*)g_q + (size_t)(bh * Tn + q0) * 16;
#pragma unroll
    for (int i = 0; i < 8; i++) {
        int l2 = tid + i * 256;
        int r = l2 >> 4, c = l2 & 15;
        *(unsigned*)&Qs[r][c * 2] = gq[l2];
    }
    __syncthreads();

    unsigned qa[2][4];
#pragma unroll
    for (int kb = 0; kb < 2; kb++) {
        qa[kb][0] = *(const unsigned*)&Qs[r0    ][kb*16 + tg*2];
        qa[kb][1] = *(const unsigned*)&Qs[r0 + 8][kb*16 + tg*2];
        qa[kb][2] = *(const unsigned*)&Qs[r0    ][kb*16 + tg*2 + 8];
        qa[kb][3] = *(const unsigned*)&Qs[r0 + 8][kb*16 + tg*2 + 8];
    }

    // ldmatrix lane-role constants (row = lane&7, matrix = lane>>3)
    const int lrow = lane & 7, lmat = lane >> 3;
    const unsigned ks_addr0 = (unsigned)__cvta_generic_to_shared(
        &Ks[0][lrow][lmat * 8]);                          // + nb*8*80 per nb; +5120 per buf
    const unsigned vt_addr0 = (unsigned)__cvta_generic_to_shared(
        &Vt[0][lrow][lmat * 8]);                          // + nb2*8*144 per nb2; +32*2 for k2..3

    const unsigned ONE2 = 0x3C003C00u;
    float o[4][4];
    float lsum[4] = {0.f, 0.f, 0.f, 0.f};
#pragma unroll
    for (int i = 0; i < 4; i++)
#pragma unroll
        for (int j = 0; j < 4; j++) o[i][j] = 0.f;

    for (int kt = 0; kt < NT; kt++) {
        const int buf = kt & 1;
        if (kt + 1 < NT) {
            const int nb_ = buf ^ 1;
            cpa16((unsigned)__cvta_generic_to_shared(&Ks[nb_][krow][kchk*8]),
                  gkb + (size_t)((kt+1)*BK + krow) * 32 + kchk * 8);
            cpa16((unsigned)__cvta_generic_to_shared(&Vt[nb_][vrow][vchk*8]),
                  gvb + (size_t)vrow * Tn + (kt+1)*BK + vchk * 8);
            cp_commit();
            asm volatile("cp.async.wait_group 1;\n");
        } else {
            asm volatile("cp.async.wait_group 0;\n");
        }
        __syncthreads();

        // S = Q @ K^T  — K fragments via ldmatrix.x4 (b0k0,b1k0,b0k1,b1k1 per nb)
        const unsigned ksb = ks_addr0 + buf * 5120;
        float s[8][4];
#pragma unroll
        for (int nb = 0; nb < 8; nb++) {
            unsigned kf[4];
            ldsm4(kf, ksb + nb * 640);
            s[nb][0] = s[nb][1] = s[nb][2] = s[nb][3] = 0.f;
            mma_bf(s[nb], qa[0], kf[0], kf[1]);
            mma_bf(s[nb], qa[1], kf[2], kf[3]);
        }

        // P = 2^S (f16), row sums via ones-B mma
        unsigned pa[4][4];
#pragma unroll
        for (int kb2 = 0; kb2 < 4; kb2++) {
            pa[kb2][0] = ex2h2(packh(s[2*kb2    ][0], s[2*kb2    ][1]));
            pa[kb2][1] = ex2h2(packh(s[2*kb2    ][2], s[2*kb2    ][3]));
            pa[kb2][2] = ex2h2(packh(s[2*kb2 + 1][0], s[2*kb2 + 1][1]));
            pa[kb2][3] = ex2h2(packh(s[2*kb2 + 1][2], s[2*kb2 + 1][3]));
        }
#pragma unroll
        for (int kb2 = 0; kb2 < 4; kb2++)
            mma_f16(lsum, pa[kb2], ONE2, ONE2);

        // O += P @ V — V fragments via 2x ldmatrix.x4 per nb2
        const unsigned vtb = vt_addr0 + buf * 4608;
#pragma unroll
        for (int nb2 = 0; nb2 < 4; nb2++) {
            unsigned vf0[4], vf1[4];
            ldsm4(vf0, vtb + nb2 * 1152);
            ldsm4(vf1, vtb + nb2 * 1152 + 64);
            mma_f16(o[nb2], pa[0], vf0[0], vf0[1]);
            mma_f16(o[nb2], pa[1], vf0[2], vf0[3]);
            mma_f16(o[nb2], pa[2], vf1[0], vf1[1]);
            mma_f16(o[nb2], pa[3], vf1[2], vf1[3]);
        }
        __syncthreads();
    }

    const float i0 = 1.f / lsum[0], i1 = 1.f / lsum[2];
    const int b = bh >> 1, hh = bh & 1;
    float* o0 = g_ctx + (size_t)(b * Tn + q0 + r0) * 64 + hh * 32;
    float* o1 = o0 + 8 * 64;
#pragma unroll
    for (int nb2 = 0; nb2 < 4; nb2++) {
        int col = nb2 * 8 + tg * 2;
        *(float2*)(o0 + col) = make_float2(o[nb2][0] * i0, o[nb2][1] * i0);
        *(float2*)(o1 + col) = make_float2(o[nb2][2] * i1, o[nb2][3] * i1);
    }
}

// ---------------- K3: tensor-core out-proj + boundary MLP (tf32 mma) ----------
__global__ __launch_bounds__(256) void k3_tc(
    const float* __restrict__ ow, const float* __restrict__ ob,
    const float* __restrict__ w1, const float* __restrict__ b1,
    const float* __restrict__ w2, const float* __restrict__ b2p)
{
    extern __shared__ float sm3[];
    float (*s_cx)[68] = (float(*)[68])sm3;          // 128 x 68 (ctx, then attn in place)
    float* s_owp = sm3 + 128*68;                    // 64 x 68, tf32-rounded, [n][k]
    float* s_w1p = s_owp + 64*68;                   // 32 x 68, tf32-rounded
    float* s_ob  = s_w1p + 32*68;                   // 64
    float* s_b1  = s_ob + 64;                       // 32
    float* s_w2  = s_b1 + 32;                       // 32
    float* s_b2  = s_w2 + 32;                       // 1

    const int tid = threadIdx.x;
    const int w = tid >> 5, lane = tid & 31;
    const int g = lane >> 2, tg = lane & 3;
    const int base = blockIdx.x * 128;

    for (int i = tid; i < 4096; i += 256)
        s_owp[(i >> 6) * 68 + (i & 63)] = __uint_as_float(tf32r(ow[i]));
    for (int i = tid; i < 2048; i += 256)
        s_w1p[(i >> 6) * 68 + (i & 63)] = __uint_as_float(tf32r(w1[i]));
    if (tid < 64) s_ob[tid] = ob[tid];
    if (tid < 32) { s_b1[tid] = b1[tid]; s_w2[tid] = w2[tid]; }
    if (tid == 0) s_b2[0] = b2p[0];
    {
        const float4* cp = (const float4*)(g_ctx + (size_t)base * 64);
        for (int i = tid; i < 2048; i += 256) {
            int r = i >> 4, c4 = i & 15;
            *(float4*)&s_cx[r][c4 * 4] = cp[i];
        }
    }
    __syncthreads();

    const int r0 = w * 16;

    unsigned af[8][4];
#pragma unroll
    for (int kb = 0; kb < 8; kb++) {
        af[kb][0] = tf32r(s_cx[r0 + g    ][kb*8 + tg]);
        af[kb][1] = tf32r(s_cx[r0 + g + 8][kb*8 + tg]);
        af[kb][2] = tf32r(s_cx[r0 + g    ][kb*8 + tg + 4]);
        af[kb][3] = tf32r(s_cx[r0 + g + 8][kb*8 + tg + 4]);
    }

    float c[8][4];
#pragma unroll
    for (int nb = 0; nb < 8; nb++) {
        c[nb][0] = c[nb][1] = c[nb][2] = c[nb][3] = 0.f;
#pragma unroll
        for (int kb = 0; kb < 8; kb++) {
            unsigned b0 = __float_as_uint(s_owp[(nb*8 + g)*68 + kb*8 + tg]);
            unsigned b1v = __float_as_uint(s_owp[(nb*8 + g)*68 + kb*8 + tg + 4]);
            mma_tf(c[nb], af[kb], b0, b1v);
        }
    }

    {
        float* a0p = g_attn + (size_t)(base + r0 + g) * 64;
        float* a1p = a0p + 8 * 64;
#pragma unroll
        for (int nb = 0; nb < 8; nb++) {
            int col = nb * 8 + tg * 2;
            c[nb][0] += s_ob[col]; c[nb][1] += s_ob[col + 1];
            c[nb][2] += s_ob[col]; c[nb][3] += s_ob[col + 1];
            *(float2*)(a0p + col) = make_float2(c[nb][0], c[nb][1]);
            *(float2*)(a1p + col) = make_float2(c[nb][2], c[nb][3]);
            s_cx[r0 + g    ][col] = c[nb][0]; s_cx[r0 + g    ][col+1] = c[nb][1];
            s_cx[r0 + g + 8][col] = c[nb][2]; s_cx[r0 + g + 8][col+1] = c[nb][3];
        }
    }
    __syncwarp();

#pragma unroll
    for (int kb = 0; kb < 8; kb++) {
        af[kb][0] = tf32r(s_cx[r0 + g    ][kb*8 + tg]);
        af[kb][1] = tf32r(s_cx[r0 + g + 8][kb*8 + tg]);
        af[kb][2] = tf32r(s_cx[r0 + g    ][kb*8 + tg + 4]);
        af[kb][3] = tf32r(s_cx[r0 + g + 8][kb*8 + tg + 4]);
    }

    float h[4][4];
#pragma unroll
    for (int nb = 0; nb < 4; nb++) {
        h[nb][0] = h[nb][1] = h[nb][2] = h[nb][3] = 0.f;
#pragma unroll
        for (int kb = 0; kb < 8; kb++) {
            unsigned b0 = __float_as_uint(s_w1p[(nb*8 + g)*68 + kb*8 + tg]);
            unsigned b1v = __float_as_uint(s_w1p[(nb*8 + g)*68 + kb*8 + tg + 4]);
            mma_tf(h[nb], af[kb], b0, b1v);
        }
    }

    float z0 = 0.f, z1 = 0.f;
#pragma unroll
    for (int nb = 0; nb < 4; nb++) {
        int col = nb * 8 + tg * 2;
        z0 += s_w2[col]   * fmaxf(h[nb][0] + s_b1[col],   0.f)
            + s_w2[col+1] * fmaxf(h[nb][1] + s_b1[col+1], 0.f);
        z1 += s_w2[col]   * fmaxf(h[nb][2] + s_b1[col],   0.f)
            + s_w2[col+1] * fmaxf(h[nb][3] + s_b1[col+1], 0.f);
    }
    z0 += __shfl_xor_sync(0xffffffffu, z0, 1);
    z0 += __shfl_xor_sync(0xffffffffu, z0, 2);
    z1 += __shfl_xor_sync(0xffffffffu, z1, 1);
    z1 += __shfl_xor_sync(0xffffffffu, z1, 2);

    if (tg == 0) {
        const float b2v = s_b2[0];
        int pos0 = base + r0 + g;
        int t0 = pos0 & (Tn - 1);
        g_start[pos0] = (t0 == 0) || (t0 <= Tn - 2 && z0 + b2v > -1.38629436f);
        int pos1 = pos0 + 8;
        int t1 = pos1 & (Tn - 1);
        g_start[pos1] = (t1 == 0) || (t1 <= Tn - 2 && z1 + b2v > -1.38629436f);
    }
}

// ---------------- K4a: per-batch ballot scan -> segment boundary list ----------------
__global__ __launch_bounds__(1024) void k4a_scan()
{
    const int b = blockIdx.x;
    const int t = threadIdx.x;
    const int lane = t & 31, wid = t >> 5;
    __shared__ int s_wcnt[32];
    __shared__ int s_woff[32];

    const int v = g_start[b * Tn + t];
    const unsigned m = __ballot_sync(0xffffffffu, v);
    const int pre = __popc(m & ((1u << lane) - 1u));
    if (lane == 0) s_wcnt[wid] = __popc(m);
    __syncthreads();
    if (t < 32) {
        int c = s_wcnt[t];
        int inc = c;
#pragma unroll
        for (int off = 1; off < 32; off <<= 1) {
            int n = __shfl_up_sync(0xffffffffu, inc, off);
            if (t >= off) inc += n;
        }
        s_woff[t] = inc - c;
        if (t == 31) {
            g_nseg[b] = inc;
            g_first[b * (Tn + 1) + inc] = Tn;
        }
    }
    __syncthreads();
    if (v) g_first[b * (Tn + 1) + s_woff[wid] + pre] = t;
}

// ---------------- K4c: fused segment-mean + final projection ----------------
__global__ __launch_bounds__(256) void k4c_meanproj(
    const float* __restrict__ pw, const float* __restrict__ pb,
    float* __restrict__ out)
{
    __shared__ float s_w[64 * 65];
    __shared__ float s_b[64];
    const int tid = threadIdx.x;
    for (int i = tid; i < 4096; i += 256)
        s_w[(i >> 6) * 65 + (i & 63)] = pw[i];
    if (tid < 64) s_b[tid] = pb[tid];
    __syncthreads();

    const int b = blockIdx.x;
    const int wid = tid >> 5, lane = tid & 31;
    const int nseg = g_nseg[b];
    const int* fst = g_first + b * (Tn + 1);

    for (int s = blockIdx.y * 8 + wid; s < Tn; s += 16 * 8) {
        float* op = out + (size_t)(b * Tn + s) * 64;
        if (s >= nseg) {
            op[lane]      = s_b[lane];
            op[lane + 32] = s_b[lane + 32];
            continue;
        }
        const int t0 = fst[s], t1 = fst[s + 1];
        float f0 = 0.f, f1 = 0.f;
        for (int t = t0; t < t1; t++) {
            const float* row = g_attn + (size_t)(b * Tn + t) * 64;
            f0 += row[lane];
            f1 += row[lane + 32];
        }
        const float inv = 1.f / (float)(t1 - t0);
        f0 *= inv; f1 *= inv;

        float a0 = s_b[lane], a1 = s_b[lane + 32];
        const float* w0 = s_w + lane * 65;
        const float* w1 = s_w + (lane + 32) * 65;
#pragma unroll
        for (int d = 0; d < 32; d++) {
            float md = __shfl_sync(0xffffffffu, f0, d);
            a0 += md * w0[d];
            a1 += md * w1[d];
        }
#pragma unroll
        for (int d = 0; d < 32; d++) {
            float md = __shfl_sync(0xffffffffu, f1, d);
            a0 += md * w0[32 + d];
            a1 += md * w1[32 + d];
        }
        op[lane]      = a0;
        op[lane + 32] = a1;
    }
}

// ---------------- launch ----------------
extern "C" void kernel_launch(void* const* d_in, const int* in_sizes, int n_in,
                              void* d_out, int out_size)
{
    const float* x    = (const float*)d_in[0];
    const float* w_in = (const float*)d_in[1];
    const float* b_in = (const float*)d_in[2];
    const float* ipw  = (const float*)d_in[3];
    const float* ipb  = (const float*)d_in[4];
    const float* ow   = (const float*)d_in[5];
    const float* ob   = (const float*)d_in[6];
    const float* w1   = (const float*)d_in[7];
    const float* b1   = (const float*)d_in[8];
    const float* w2   = (const float*)d_in[9];
    const float* b2   = (const float*)d_in[10];
    const float* pw   = (const float*)d_in[11];
    const float* pb   = (const float*)d_in[12];
    float* out = (float*)d_out;

    const int smem1 = (192*INDIM + 192) * 4 + 128 * 194 * 2;  // ~55.9 KB
    cudaFuncSetAttribute(k1_qkv, cudaFuncAttributeMaxDynamicSharedMemorySize, smem1);
    const int smem3 = (128*68 + 64*68 + 32*68 + 64 + 32 + 32 + 1) * 4;  // ~61.5 KB
    cudaFuncSetAttribute(k3_tc, cudaFuncAttributeMaxDynamicSharedMemorySize, smem3);

    k0_fold<<<6, 256>>>(w_in, b_in, ipw, ipb);
    k1_qkv<<<(Bn * Tn) / 128, 128, smem1>>>(x);
    dim3 g2(Tn / BQ, Bn * NH);
    k2_attn<<<g2, 256>>>();
    k3_tc<<<(Bn * Tn) / 128, 256, smem3>>>(ow, ob, w1, b1, w2, b2);
    k4a_scan<<<Bn, 1024>>>();
    dim3 g4(Bn, 16);
    k4c_meanproj<<<g4, 256>>>(pw, pb, out);
}

// round 11
// speedup vs baseline: 1.0779x; 1.0286x over previous
#include <cuda_runtime.h>
#include <cuda_bf16.h>
#include <cuda_fp16.h>

#define Bn   64
#define Tn   1024
#define INDIM 7
#define EMB  64
#define NH   2
#define DHd  32

// ---------------- scratch (static device globals; no allocations) ----------------
__device__ __nv_bfloat16 g_q[Bn*NH*Tn*DHd];   // [bh][t][d], prescaled by log2e/sqrt(32)
__device__ __nv_bfloat16 g_k[Bn*NH*Tn*DHd];   // [bh][t][d]
__device__ __half        g_vt[Bn*NH*DHd*Tn];  // [bh][d][t]  (V transposed, f16)
__device__ float g_ctx[Bn*Tn*EMB];            // [b][t][h*32+d]
__device__ float g_attn[Bn*Tn*EMB];           // attn_out
__device__ int   g_start[Bn*Tn];
__device__ int   g_nseg[Bn];
__device__ int   g_first[Bn*(Tn+1)];          // segment start positions per batch
__device__ float g_wc[192*INDIM];             // folded qkv weight [192][7]
__device__ float g_bc[192];                   // folded qkv bias

__device__ __forceinline__ unsigned packbf(float x, float y) {
    __nv_bfloat162 h = __floats2bfloat162_rn(x, y);
    return *(unsigned*)&h;
}
__device__ __forceinline__ unsigned packh(float x, float y) {  // lo=x, hi=y (f16x2)
    unsigned r;
    asm("cvt.rn.f16x2.f32 %0, %1, %2;" : "=r"(r) : "f"(y), "f"(x));
    return r;
}
__device__ __forceinline__ unsigned ex2h2(unsigned v) {
    unsigned r; asm("ex2.approx.f16x2 %0, %1;" : "=r"(r) : "r"(v)); return r;
}
__device__ __forceinline__ unsigned tf32r(float f) {
    unsigned r; asm("cvt.rna.tf32.f32 %0, %1;" : "=r"(r) : "f"(f)); return r;
}
__device__ __forceinline__ void mma_bf(float* d, const unsigned* a, unsigned b0, unsigned b1) {
    asm volatile(
        "mma.sync.aligned.m16n8k16.row.col.f32.bf16.bf16.f32 "
        "{%0,%1,%2,%3}, {%4,%5,%6,%7}, {%8,%9}, {%0,%1,%2,%3};\n"
        : "+f"(d[0]), "+f"(d[1]), "+f"(d[2]), "+f"(d[3])
        : "r"(a[0]), "r"(a[1]), "r"(a[2]), "r"(a[3]), "r"(b0), "r"(b1));
}
__device__ __forceinline__ void mma_f16(float* d, const unsigned* a, unsigned b0, unsigned b1) {
    asm volatile(
        "mma.sync.aligned.m16n8k16.row.col.f32.f16.f16.f32 "
        "{%0,%1,%2,%3}, {%4,%5,%6,%7}, {%8,%9}, {%0,%1,%2,%3};\n"
        : "+f"(d[0]), "+f"(d[1]), "+f"(d[2]), "+f"(d[3])
        : "r"(a[0]), "r"(a[1]), "r"(a[2]), "r"(a[3]), "r"(b0), "r"(b1));
}
__device__ __forceinline__ void mma_tf(float* d, const unsigned* a, unsigned b0, unsigned b1) {
    asm volatile(
        "mma.sync.aligned.m16n8k8.row.col.f32.tf32.tf32.f32 "
        "{%0,%1,%2,%3}, {%4,%5,%6,%7}, {%8,%9}, {%0,%1,%2,%3};\n"
        : "+f"(d[0]), "+f"(d[1]), "+f"(d[2]), "+f"(d[3])
        : "r"(a[0]), "r"(a[1]), "r"(a[2]), "r"(a[3]), "r"(b0), "r"(b1));
}
__device__ __forceinline__ void ldsm4(unsigned* r, unsigned addr) {
    asm volatile("ldmatrix.sync.aligned.m8n8.x4.shared.b16 {%0,%1,%2,%3}, [%4];\n"
        : "=r"(r[0]), "=r"(r[1]), "=r"(r[2]), "=r"(r[3]) : "r"(addr));
}
__device__ __forceinline__ void cpa16(unsigned dst, const void* src) {
    asm volatile("cp.async.cg.shared.global [%0], [%1], 16;\n" :: "r"(dst), "l"(src));
}
__device__ __forceinline__ void cp_commit() { asm volatile("cp.async.commit_group;\n"); }

// ---------------- K0: fold the two input linears into one 7->192 ----------------
__global__ __launch_bounds__(256) void k0_fold(
    const float* __restrict__ w_in, const float* __restrict__ b_in,
    const float* __restrict__ ipw, const float* __restrict__ ipb)
{
    const int gid = blockIdx.x * 256 + threadIdx.x;
    if (gid < 192 * INDIM) {
        const int o = gid / INDIM, j = gid % INDIM;
        float s = 0.f;
#pragma unroll
        for (int e = 0; e < 64; e++) s += ipw[o*64 + e] * w_in[e*INDIM + j];
        g_wc[gid] = s;
    } else if (gid < 192 * INDIM + 192) {
        const int o = gid - 192 * INDIM;
        float s = ipb[o];
#pragma unroll
        for (int e = 0; e < 64; e++) s += ipw[o*64 + e] * b_in[e];
        g_bc[o] = s;
    }
}

// ---------------- K1: x -> qkv via folded weights (q,k bf16; v f16 transposed) ----
__global__ __launch_bounds__(128) void k1_qkv(const float* __restrict__ x)
{
    extern __shared__ float sm[];
    float* s_wc = sm;                 // 1344
    float* s_bc = s_wc + 192*INDIM;   // 192
    unsigned short* s_qkv = (unsigned short*)(s_bc + 192);  // 128 x 194 raw 16-bit

    const int tid = threadIdx.x;
    for (int i = tid; i < 192*INDIM; i += 128) s_wc[i] = g_wc[i];
    for (int i = tid; i < 192;       i += 128) s_bc[i] = g_bc[i];
    __syncthreads();

    const int pos = blockIdx.x * 128 + tid;
    float xv[INDIM];
    const float* xp = x + (size_t)pos * INDIM;
#pragma unroll
    for (int j = 0; j < INDIM; j++) xv[j] = xp[j];

    const float QSCALE = 0.25506363f;  // log2(e)/sqrt(32)
    unsigned short* row = s_qkv + tid * 194;
#pragma unroll
    for (int j0 = 0; j0 < 192; j0 += 4) {
        float a0 = s_bc[j0], a1 = s_bc[j0+1], a2 = s_bc[j0+2], a3 = s_bc[j0+3];
#pragma unroll
        for (int j = 0; j < INDIM; j++) {
            float xj = xv[j];
            a0 += s_wc[(j0+0)*INDIM + j] * xj;
            a1 += s_wc[(j0+1)*INDIM + j] * xj;
            a2 += s_wc[(j0+2)*INDIM + j] * xj;
            a3 += s_wc[(j0+3)*INDIM + j] * xj;
        }
        if (j0 < 64) { a0 *= QSCALE; a1 *= QSCALE; a2 *= QSCALE; a3 *= QSCALE; }
        if (j0 < 128) {   // q,k -> bf16
            *(unsigned*)&row[j0]     = packbf(a0, a1);
            *(unsigned*)&row[j0 + 2] = packbf(a2, a3);
        } else {          // v -> f16
            *(unsigned*)&row[j0]     = packh(a0, a1);
            *(unsigned*)&row[j0 + 2] = packh(a2, a3);
        }
    }
    __syncthreads();

    const int b  = blockIdx.x >> 3;
    const int t0 = (blockIdx.x & 7) * 128;
    unsigned* uq = (unsigned*)g_q;
    unsigned* uk = (unsigned*)g_k;
#pragma unroll
    for (int hh = 0; hh < 2; hh++) {
        const int dst = (b*2 + hh) * (Tn*DHd/2) + t0 * 16;
        for (int l2 = tid; l2 < 2048; l2 += 128) {
            int tt = l2 >> 4, dp = l2 & 15;
            const unsigned short* r = s_qkv + tt * 194;
            uq[dst + l2] = *(const unsigned*)&r[       hh*32 + dp*2];
            uk[dst + l2] = *(const unsigned*)&r[ 64  + hh*32 + dp*2];
        }
    }
    // V transposed writeout: g_vt[bh][d][t]
    unsigned* uvt = (unsigned*)g_vt;
    for (int idx = tid; idx < 4096; idx += 128) {
        int p = idx >> 6, tp = idx & 63;
        int hh = p >> 5, d = p & 31;
        unsigned short lo = s_qkv[(2*tp    ) * 194 + 128 + hh*32 + d];
        unsigned short hi = s_qkv[(2*tp + 1) * 194 + 128 + hh*32 + d];
        uvt[(b*2 + hh) * 16384 + d * 512 + (t0 >> 1) + tp] =
            (unsigned)lo | ((unsigned)hi << 16);
    }
}

// ---------------- K2: flash attention, ldmatrix frags, cp.async pipe ----------
#define BQ 128
#define BK 64
#define NT (Tn / BK)
__global__ __launch_bounds__(256) void k2_attn()
{
    __shared__ __nv_bfloat16 Qs[BQ][40];
    __shared__ __nv_bfloat16 Ks[2][BK][40];
    __shared__ __half        Vt[2][32][72];

    const int tid = threadIdx.x;
    const int wid = tid >> 5, lane = tid & 31;
    const int g = lane >> 2, tg = lane & 3;
    const int bh = blockIdx.y;
    const int q0 = blockIdx.x * BQ;
    const int r0 = wid * 16 + g;

    const int krow = tid >> 2, kchk = tid & 3;
    const int vrow = tid >> 3, vchk = tid & 7;
    const __nv_bfloat16* gkb = (const __nv_bfloat16*)g_k + (size_t)bh * Tn * 32;
    const __half*        gvb = (const __half*)g_vt + (size_t)bh * 32 * Tn;

    {
        cpa16((unsigned)__cvta_generic_to_shared(&Ks[0][krow][kchk*8]),
              gkb + (size_t)krow * 32 + kchk * 8);
        cpa16((unsigned)__cvta_generic_to_shared(&Vt[0][vrow][vchk*8]),
              gvb + (size_t)vrow * Tn + vchk * 8);
        cp_commit();
    }

    const unsigned* gq = (const unsigned*)g_q + (size_t)(bh * Tn + q0) * 16;
#pragma unroll
    for (int i = 0; i < 8; i++) {
        int l2 = tid + i * 256;
        int r = l2 >> 4, c = l2 & 15;
        *(unsigned*)&Qs[r][c * 2] = gq[l2];
    }
    __syncthreads();

    unsigned qa[2][4];
#pragma unroll
    for (int kb = 0; kb < 2; kb++) {
        qa[kb][0] = *(const unsigned*)&Qs[r0    ][kb*16 + tg*2];
        qa[kb][1] = *(const unsigned*)&Qs[r0 + 8][kb*16 + tg*2];
        qa[kb][2] = *(const unsigned*)&Qs[r0    ][kb*16 + tg*2 + 8];
        qa[kb][3] = *(const unsigned*)&Qs[r0 + 8][kb*16 + tg*2 + 8];
    }

    const int lrow = lane & 7, lmat = lane >> 3;
    const unsigned ks_addr0 = (unsigned)__cvta_generic_to_shared(
        &Ks[0][lrow][lmat * 8]);
    const unsigned vt_addr0 = (unsigned)__cvta_generic_to_shared(
        &Vt[0][lrow][lmat * 8]);

    const unsigned ONE2 = 0x3C003C00u;
    float o[4][4];
    float lsum[4] = {0.f, 0.f, 0.f, 0.f};
#pragma unroll
    for (int i = 0; i < 4; i++)
#pragma unroll
        for (int j = 0; j < 4; j++) o[i][j] = 0.f;

    for (int kt = 0; kt < NT; kt++) {
        const int buf = kt & 1;
        if (kt + 1 < NT) {
            const int nb_ = buf ^ 1;
            cpa16((unsigned)__cvta_generic_to_shared(&Ks[nb_][krow][kchk*8]),
                  gkb + (size_t)((kt+1)*BK + krow) * 32 + kchk * 8);
            cpa16((unsigned)__cvta_generic_to_shared(&Vt[nb_][vrow][vchk*8]),
                  gvb + (size_t)vrow * Tn + (kt+1)*BK + vchk * 8);
            cp_commit();
            asm volatile("cp.async.wait_group 1;\n");
        } else {
            asm volatile("cp.async.wait_group 0;\n");
        }
        __syncthreads();

        const unsigned ksb = ks_addr0 + buf * 5120;
        float s[8][4];
#pragma unroll
        for (int nb = 0; nb < 8; nb++) {
            unsigned kf[4];
            ldsm4(kf, ksb + nb * 640);
            s[nb][0] = s[nb][1] = s[nb][2] = s[nb][3] = 0.f;
            mma_bf(s[nb], qa[0], kf[0], kf[1]);
            mma_bf(s[nb], qa[1], kf[2], kf[3]);
        }

        unsigned pa[4][4];
#pragma unroll
        for (int kb2 = 0; kb2 < 4; kb2++) {
            pa[kb2][0] = ex2h2(packh(s[2*kb2    ][0], s[2*kb2    ][1]));
            pa[kb2][1] = ex2h2(packh(s[2*kb2    ][2], s[2*kb2    ][3]));
            pa[kb2][2] = ex2h2(packh(s[2*kb2 + 1][0], s[2*kb2 + 1][1]));
            pa[kb2][3] = ex2h2(packh(s[2*kb2 + 1][2], s[2*kb2 + 1][3]));
        }
#pragma unroll
        for (int kb2 = 0; kb2 < 4; kb2++)
            mma_f16(lsum, pa[kb2], ONE2, ONE2);

        const unsigned vtb = vt_addr0 + buf * 4608;
#pragma unroll
        for (int nb2 = 0; nb2 < 4; nb2++) {
            unsigned vf0[4], vf1[4];
            ldsm4(vf0, vtb + nb2 * 1152);
            ldsm4(vf1, vtb + nb2 * 1152 + 64);
            mma_f16(o[nb2], pa[0], vf0[0], vf0[1]);
            mma_f16(o[nb2], pa[1], vf0[2], vf0[3]);
            mma_f16(o[nb2], pa[2], vf1[0], vf1[1]);
            mma_f16(o[nb2], pa[3], vf1[2], vf1[3]);
        }
        __syncthreads();
    }

    const float i0 = 1.f / lsum[0], i1 = 1.f / lsum[2];
    const int b = bh >> 1, hh = bh & 1;
    float* o0 = g_ctx + (size_t)(b * Tn + q0 + r0) * 64 + hh * 32;
    float* o1 = o0 + 8 * 64;
#pragma unroll
    for (int nb2 = 0; nb2 < 4; nb2++) {
        int col = nb2 * 8 + tg * 2;
        *(float2*)(o0 + col) = make_float2(o[nb2][0] * i0, o[nb2][1] * i0);
        *(float2*)(o1 + col) = make_float2(o[nb2][2] * i1, o[nb2][3] * i1);
    }
}

// ---------------- K3: out-proj (tf32, A direct from gmem) + MLP (bf16, A from C-frags) ----
// No ctx/attn smem staging at all. smem = weights only (~22.5 KB, static).
// GEMM2's bf16 A-fragments are GEMM1's C-fragments packed pairwise (layout identity).
__global__ __launch_bounds__(256) void k3_tc(
    const float* __restrict__ ow, const float* __restrict__ ob,
    const float* __restrict__ w1, const float* __restrict__ b1,
    const float* __restrict__ w2, const float* __restrict__ b2p)
{
    __shared__ float    s_owp[64 * 68];   // tf32-rounded out_w [n][k], pad 68
    __shared__ unsigned s_w1bf[32 * 36];  // bf16-pair w1 [n][kpair], pad 36
    __shared__ float    s_ob[64], s_b1[32], s_w2[32], s_b2[1];

    const int tid = threadIdx.x;
    const int w = tid >> 5, lane = tid & 31;
    const int g = lane >> 2, tg = lane & 3;
    const int base = blockIdx.x * 128;
    const int r0 = w * 16;

    for (int i = tid; i < 4096; i += 256)
        s_owp[(i >> 6) * 68 + (i & 63)] = __uint_as_float(tf32r(ow[i]));
    for (int i = tid; i < 1024; i += 256) {
        int n = i >> 5, kp = i & 31;
        s_w1bf[n * 36 + kp] = packbf(w1[n * 64 + kp * 2], w1[n * 64 + kp * 2 + 1]);
    }
    if (tid < 64) s_ob[tid] = ob[tid];
    if (tid < 32) { s_b1[tid] = b1[tid]; s_w2[tid] = w2[tid]; }
    if (tid == 0) s_b2[0] = b2p[0];

    // A fragments (ctx) straight from gmem, tf32 (overlaps with smem fill)
    const float* cx0 = g_ctx + (size_t)(base + r0 + g) * 64;
    const float* cx1 = cx0 + 8 * 64;
    unsigned af[8][4];
#pragma unroll
    for (int kb = 0; kb < 8; kb++) {
        af[kb][0] = tf32r(cx0[kb*8 + tg]);
        af[kb][1] = tf32r(cx1[kb*8 + tg]);
        af[kb][2] = tf32r(cx0[kb*8 + tg + 4]);
        af[kb][3] = tf32r(cx1[kb*8 + tg + 4]);
    }
    __syncthreads();

    // GEMM1: attn = ctx @ ow^T
    float c[8][4];
#pragma unroll
    for (int nb = 0; nb < 8; nb++) {
        c[nb][0] = c[nb][1] = c[nb][2] = c[nb][3] = 0.f;
#pragma unroll
        for (int kb = 0; kb < 8; kb++) {
            unsigned b0 = __float_as_uint(s_owp[(nb*8 + g)*68 + kb*8 + tg]);
            unsigned b1v = __float_as_uint(s_owp[(nb*8 + g)*68 + kb*8 + tg + 4]);
            mma_tf(c[nb], af[kb], b0, b1v);
        }
    }

    // bias + write g_attn (fp32, exact path for segment means)
    {
        float* a0p = g_attn + (size_t)(base + r0 + g) * 64;
        float* a1p = a0p + 8 * 64;
#pragma unroll
        for (int nb = 0; nb < 8; nb++) {
            int col = nb * 8 + tg * 2;
            c[nb][0] += s_ob[col]; c[nb][1] += s_ob[col + 1];
            c[nb][2] += s_ob[col]; c[nb][3] += s_ob[col + 1];
            *(float2*)(a0p + col) = make_float2(c[nb][0], c[nb][1]);
            *(float2*)(a1p + col) = make_float2(c[nb][2], c[nb][3]);
        }
    }

    // GEMM2 A-fragments = C-fragments packed to bf16 (layout identity, no smem)
    unsigned af16[4][4];
#pragma unroll
    for (int kb = 0; kb < 4; kb++) {
        af16[kb][0] = packbf(c[2*kb    ][0], c[2*kb    ][1]);
        af16[kb][1] = packbf(c[2*kb    ][2], c[2*kb    ][3]);
        af16[kb][2] = packbf(c[2*kb + 1][0], c[2*kb + 1][1]);
        af16[kb][3] = packbf(c[2*kb + 1][2], c[2*kb + 1][3]);
    }

    // GEMM2: hidden [16 x 32] = attn @ w1^T  (bf16)
    float h[4][4];
#pragma unroll
    for (int nb = 0; nb < 4; nb++) {
        h[nb][0] = h[nb][1] = h[nb][2] = h[nb][3] = 0.f;
#pragma unroll
        for (int kb = 0; kb < 4; kb++) {
            unsigned b0 = s_w1bf[(nb*8 + g)*36 + kb*8 + tg];
            unsigned b1v = s_w1bf[(nb*8 + g)*36 + kb*8 + tg + 4];
            mma_bf(h[nb], af16[kb], b0, b1v);
        }
    }

    // z = b2 + sum w2 * relu(h + b1); quad reduce
    float z0 = 0.f, z1 = 0.f;
#pragma unroll
    for (int nb = 0; nb < 4; nb++) {
        int col = nb * 8 + tg * 2;
        z0 += s_w2[col]   * fmaxf(h[nb][0] + s_b1[col],   0.f)
            + s_w2[col+1] * fmaxf(h[nb][1] + s_b1[col+1], 0.f);
        z1 += s_w2[col]   * fmaxf(h[nb][2] + s_b1[col],   0.f)
            + s_w2[col+1] * fmaxf(h[nb][3] + s_b1[col+1], 0.f);
    }
    z0 += __shfl_xor_sync(0xffffffffu, z0, 1);
    z0 += __shfl_xor_sync(0xffffffffu, z0, 2);
    z1 += __shfl_xor_sync(0xffffffffu, z1, 1);
    z1 += __shfl_xor_sync(0xffffffffu, z1, 2);

    if (tg == 0) {
        const float b2v = s_b2[0];
        int pos0 = base + r0 + g;
        int t0 = pos0 & (Tn - 1);
        g_start[pos0] = (t0 == 0) || (t0 <= Tn - 2 && z0 + b2v > -1.38629436f);
        int pos1 = pos0 + 8;
        int t1 = pos1 & (Tn - 1);
        g_start[pos1] = (t1 == 0) || (t1 <= Tn - 2 && z1 + b2v > -1.38629436f);
    }
}

// ---------------- K4a: per-batch ballot scan -> segment boundary list ----------------
__global__ __launch_bounds__(1024) void k4a_scan()
{
    const int b = blockIdx.x;
    const int t = threadIdx.x;
    const int lane = t & 31, wid = t >> 5;
    __shared__ int s_wcnt[32];
    __shared__ int s_woff[32];

    const int v = g_start[b * Tn + t];
    const unsigned m = __ballot_sync(0xffffffffu, v);
    const int pre = __popc(m & ((1u << lane) - 1u));
    if (lane == 0) s_wcnt[wid] = __popc(m);
    __syncthreads();
    if (t < 32) {
        int c = s_wcnt[t];
        int inc = c;
#pragma unroll
        for (int off = 1; off < 32; off <<= 1) {
            int n = __shfl_up_sync(0xffffffffu, inc, off);
            if (t >= off) inc += n;
        }
        s_woff[t] = inc - c;
        if (t == 31) {
            g_nseg[b] = inc;
            g_first[b * (Tn + 1) + inc] = Tn;
        }
    }
    __syncthreads();
    if (v) g_first[b * (Tn + 1) + s_woff[wid] + pre] = t;
}

// ---------------- K4c: fused segment-mean + final projection ----------------
__global__ __launch_bounds__(256) void k4c_meanproj(
    const float* __restrict__ pw, const float* __restrict__ pb,
    float* __restrict__ out)
{
    __shared__ float s_w[64 * 65];
    __shared__ float s_b[64];
    const int tid = threadIdx.x;
    for (int i = tid; i < 4096; i += 256)
        s_w[(i >> 6) * 65 + (i & 63)] = pw[i];
    if (tid < 64) s_b[tid] = pb[tid];
    __syncthreads();

    const int b = blockIdx.x;
    const int wid = tid >> 5, lane = tid & 31;
    const int nseg = g_nseg[b];
    const int* fst = g_first + b * (Tn + 1);

    for (int s = blockIdx.y * 8 + wid; s < Tn; s += 16 * 8) {
        float* op = out + (size_t)(b * Tn + s) * 64;
        if (s >= nseg) {
            op[lane]      = s_b[lane];
            op[lane + 32] = s_b[lane + 32];
            continue;
        }
        const int t0 = fst[s], t1 = fst[s + 1];
        float f0 = 0.f, f1 = 0.f;
        for (int t = t0; t < t1; t++) {
            const float* row = g_attn + (size_t)(b * Tn + t) * 64;
            f0 += row[lane];
            f1 += row[lane + 32];
        }
        const float inv = 1.f / (float)(t1 - t0);
        f0 *= inv; f1 *= inv;

        float a0 = s_b[lane], a1 = s_b[lane + 32];
        const float* w0 = s_w + lane * 65;
        const float* w1 = s_w + (lane + 32) * 65;
#pragma unroll
        for (int d = 0; d < 32; d++) {
            float md = __shfl_sync(0xffffffffu, f0, d);
            a0 += md * w0[d];
            a1 += md * w1[d];
        }
#pragma unroll
        for (int d = 0; d < 32; d++) {
            float md = __shfl_sync(0xffffffffu, f1, d);
            a0 += md * w0[32 + d];
            a1 += md * w1[32 + d];
        }
        op[lane]      = a0;
        op[lane + 32] = a1;
    }
}

// ---------------- launch ----------------
extern "C" void kernel_launch(void* const* d_in, const int* in_sizes, int n_in,
                              void* d_out, int out_size)
{
    const float* x    = (const float*)d_in[0];
    const float* w_in = (const float*)d_in[1];
    const float* b_in = (const float*)d_in[2];
    const float* ipw  = (const float*)d_in[3];
    const float* ipb  = (const float*)d_in[4];
    const float* ow   = (const float*)d_in[5];
    const float* ob   = (const float*)d_in[6];
    const float* w1   = (const float*)d_in[7];
    const float* b1   = (const float*)d_in[8];
    const float* w2   = (const float*)d_in[9];
    const float* b2   = (const float*)d_in[10];
    const float* pw   = (const float*)d_in[11];
    const float* pb   = (const float*)d_in[12];
    float* out = (float*)d_out;

    const int smem1 = (192*INDIM + 192) * 4 + 128 * 194 * 2;  // ~55.9 KB
    cudaFuncSetAttribute(k1_qkv, cudaFuncAttributeMaxDynamicSharedMemorySize, smem1);

    k0_fold<<<6, 256>>>(w_in, b_in, ipw, ipb);
    k1_qkv<<<(Bn * Tn) / 128, 128, smem1>>>(x);
    dim3 g2(Tn / BQ, Bn * NH);
    k2_attn<<<g2, 256>>>();
    k3_tc<<<(Bn * Tn) / 128, 256>>>(ow, ob, w1, b1, w2, b2);
    k4a_scan<<<Bn, 1024>>>();
    dim3 g4(Bn, 16);
    k4c_meanproj<<<g4, 256>>>(pw, pb, out);
}